// round 16
// baseline (speedup 1.0000x reference)
#include <cuda_runtime.h>
#include <stdint.h>

// RVAEModel: out[b, c, g] = weight[idx[b, g], c]
//   idx:    [256, 64]  (int32 OR int64 — detected in-warp, no extra kernel)
//   weight: fp32 [1024, 1024]
//   out:    fp32 [256, 1024, 8, 8] (= [256, 1024, 64])
//
// Block = (b, 512-wide c-half) = 8 subtiles of 64 c. 256 threads, grid 512
// = one wave (48KB smem -> 4 CTAs/SM). 3-deep cp.async ring, ONE barrier
// per subtile, exact waits (allow = {2,1,...,1,0}).
//   iter h: wait_group -> syncthreads (publishes tile h, proves tile h-1
//   consumed) -> gather(h+2) into (h-1)%3 -> LDS.128 x4 -> reg 4x4
//   transpose -> STG.128 x4 (two dense 256B segments per warp-op).
// Tile: 64 g x 16 float4 cols, physical col = c4 ^ (g>>2 mod 16); LDS
// bank-group = (uc^ub) mod 8, distinct per quarter-warp -> conflict-free.
// Dtype detect: warp votes on odd words of the FIRST 64 indices (512B probe,
// in-bounds under both interpretations). P[wrong] ~ 1024^-32.

static constexpr int BS = 256;
static constexpr int M  = 64;    // tokens per sample (g)
static constexpr int C  = 1024;  // channels
static constexpr int NT = 8;     // subtiles per block
static constexpr int SC = 64;    // subtile c-width
static constexpr int NB = 3;     // tin ring depth

__global__ __launch_bounds__(256)
void rvae_gather_transpose(const void*  __restrict__ idx_raw,
                           const float* __restrict__ w,
                           float*       __restrict__ out)
{
    const int b     = blockIdx.y;
    const int cbase = blockIdx.x * (NT * SC); // 0 or 512
    const int t     = threadIdx.x;             // 256 threads

    __shared__ __align__(128) float4 tin[NB][M * 16]; // 3 x 16KB, swizzled

    // Gather lanes: c4 = t&15 (float4 col), gb = t>>4 (0..15), g = gb + 16i.
    const int c4 = t & 15;
    const int gb = t >> 4;

    // ---- in-warp dtype detect (probe first 64 indices: 512B, in-bounds
    // under both interpretations). int64 data (values<1024) -> odd words 0;
    // int32 -> sampled odd words random nonzero w.p. 1023/1024 each.
    const unsigned int probe =
        reinterpret_cast<const unsigned int*>(idx_raw)[2 * (t & 63) + 1];
    const bool is32 = __any_sync(0xffffffffu, probe != 0u);

    int row[4];
    if (is32) {
        #pragma unroll
        for (int i = 0; i < 4; i++)
            row[i] = reinterpret_cast<const int*>(idx_raw)[b * M + gb + 16 * i];
    } else {
        #pragma unroll
        for (int i = 0; i < 4; i++)
            row[i] = (int)reinterpret_cast<const long long*>(idx_raw)[b * M + gb + 16 * i];
    }

    auto gather = [&](int h) {
        const int c0  = cbase + SC * h;
        float4*   buf = tin[h % NB];
        #pragma unroll
        for (int i = 0; i < 4; i++) {
            const int g = gb + 16 * i;
            const float*   src = w + (size_t)row[i] * C + c0 + (c4 << 2);
            const uint32_t dst = (uint32_t)__cvta_generic_to_shared(
                &buf[g * 16 + (c4 ^ ((g >> 2) & 15))]);
            asm volatile("cp.async.cg.shared.global [%0], [%1], 16;"
                         :: "r"(dst), "l"(src) : "memory");
        }
        asm volatile("cp.async.commit_group;" ::: "memory");
    };

    gather(0);
    gather(1);
    gather(2);

    // Transpose unit: 4g x 4c. ub = g-quad (0..15), uc = c-quad (0..15).
    const int ub = t & 15;
    const int uc = t >> 4;
    const int sc = uc ^ ub; // physical col of logical col uc in rows 4ub+k
                            // ((4ub+k)>>2 & 15 == ub)

    #pragma unroll
    for (int h = 0; h < NT; h++) {
        // Exact accounting: committed tiles = 0..min(h+1, NT-1); need 0..h.
        const int allow = (h == 0) ? 2 : (h < NT - 1) ? 1 : 0;
        if (allow == 2)      asm volatile("cp.async.wait_group 2;" ::: "memory");
        else if (allow == 1) asm volatile("cp.async.wait_group 1;" ::: "memory");
        else                 asm volatile("cp.async.wait_group 0;" ::: "memory");
        __syncthreads(); // publishes tile h; proves tile h-1 consumed by all

        // Buffer (h+2)%3 == (h-1)%3 is free now: refill for tile h+2.
        if (h >= 1 && h + 2 < NT) gather(h + 2);

        const float4* ti = tin[h % NB];
        const float4 r0 = ti[(4 * ub + 0) * 16 + sc];
        const float4 r1 = ti[(4 * ub + 1) * 16 + sc];
        const float4 r2 = ti[(4 * ub + 2) * 16 + sc];
        const float4 r3 = ti[(4 * ub + 3) * 16 + sc];

        // out[b, cbase + SC*h + 4*uc + j, 4*ub + k]
        float* ob = out + (size_t)b * (C * M)
                        + (size_t)(cbase + SC * h) * M + 4 * ub;
        *reinterpret_cast<float4*>(ob + (4 * uc + 0) * M) = float4{r0.x, r1.x, r2.x, r3.x};
        *reinterpret_cast<float4*>(ob + (4 * uc + 1) * M) = float4{r0.y, r1.y, r2.y, r3.y};
        *reinterpret_cast<float4*>(ob + (4 * uc + 2) * M) = float4{r0.z, r1.z, r2.z, r3.z};
        *reinterpret_cast<float4*>(ob + (4 * uc + 3) * M) = float4{r0.w, r1.w, r2.w, r3.w};
    }
}

extern "C" void kernel_launch(void* const* d_in, const int* in_sizes, int n_in,
                              void* d_out, int out_size)
{
    // indices: 16384 elements; weight: 1048576 elements (fp32)
    const void*  idx;
    const float* w;
    if (in_sizes[0] == BS * M) {
        idx = d_in[0];
        w   = (const float*)d_in[1];
    } else {
        idx = d_in[1];
        w   = (const float*)d_in[0];
    }

    dim3 grid(C / (NT * SC), BS); // (2, 256) = 512 blocks = one wave
    rvae_gather_transpose<<<grid, 256>>>(idx, w, (float*)d_out);
}